// round 1
// baseline (speedup 1.0000x reference)
#include <cuda_runtime.h>
#include <math.h>

#define BATCH 4
#define SEQ   2048
#define DIM   512

// Scratch: __device__ globals (allocation-free per harness rules)
__device__ float g_Q[BATCH * SEQ * DIM];            // 16 MB
__device__ float g_K[BATCH * SEQ * DIM];            // 16 MB
__device__ float g_V[BATCH * SEQ * DIM];            // 16 MB
__device__ float g_S[(size_t)BATCH * SEQ * SEQ];    // 64 MB

// ---------------------------------------------------------------------------
// Generic 128x128x8 SGEMM, 256 threads, 8x8 per-thread micro-tile.
// TRANS_B=false: C = alpha * A[MxK] @ B[KxN] (+bias)
// TRANS_B=true : C = alpha * A[MxK] @ B[NxK]^T (+bias)
// All dims assumed multiples of tile sizes (true for this problem).
// blockIdx.z selects batch via strides sA/sB/sC.
// ---------------------------------------------------------------------------
template <bool TRANS_B, bool HAS_BIAS, bool HAS_SCALE>
__global__ __launch_bounds__(256, 2)
void sgemm128(int M, int N, int K,
              const float* __restrict__ A, int lda, long long sA,
              const float* __restrict__ Bm, int ldb, long long sB,
              float* __restrict__ C, int ldc, long long sC,
              float alpha, const float* __restrict__ bias)
{
    A  += (long long)blockIdx.z * sA;
    Bm += (long long)blockIdx.z * sB;
    C  += (long long)blockIdx.z * sC;

    __shared__ float As[8][128];
    __shared__ float Bs[8][128];

    const int tid = threadIdx.x;
    const int bm = blockIdx.y * 128;
    const int bn = blockIdx.x * 128;

    // A tile load mapping: row in tile = tid/2, k offset = (tid&1)*4, float4
    const int arow = tid >> 1;
    const int acol = (tid & 1) * 4;
    const float* Aptr = A + (long long)(bm + arow) * lda + acol;

    // B tile load mapping
    int brow, bcol;
    const float* Bptr;
    if (TRANS_B) {
        brow = tid >> 1;          // n within tile
        bcol = (tid & 1) * 4;     // k offset
        Bptr = Bm + (long long)(bn + brow) * ldb + bcol;
    } else {
        brow = tid >> 5;          // k within tile
        bcol = (tid & 31) * 4;    // n offset
        Bptr = Bm + (long long)brow * ldb + bn + bcol;
    }

    const int tx = tid & 15;      // 16 cols of threads
    const int ty = tid >> 4;      // 16 rows of threads

    float acc[8][8];
#pragma unroll
    for (int i = 0; i < 8; i++)
#pragma unroll
        for (int j = 0; j < 8; j++) acc[i][j] = 0.f;

    for (int k0 = 0; k0 < K; k0 += 8) {
        // load A tile (transpose into As[k][m])
        float4 av = *(const float4*)(Aptr + k0);
        As[acol + 0][arow] = av.x;
        As[acol + 1][arow] = av.y;
        As[acol + 2][arow] = av.z;
        As[acol + 3][arow] = av.w;
        // load B tile into Bs[k][n]
        if (TRANS_B) {
            float4 bv = *(const float4*)(Bptr + k0);
            Bs[bcol + 0][brow] = bv.x;
            Bs[bcol + 1][brow] = bv.y;
            Bs[bcol + 2][brow] = bv.z;
            Bs[bcol + 3][brow] = bv.w;
        } else {
            float4 bv = *(const float4*)(Bptr + (long long)k0 * ldb);
            *(float4*)&Bs[brow][bcol] = bv;
        }
        __syncthreads();

#pragma unroll
        for (int kk = 0; kk < 8; kk++) {
            float af[8], bf[8];
            *(float4*)&af[0] = *(const float4*)&As[kk][ty * 4];
            *(float4*)&af[4] = *(const float4*)&As[kk][64 + ty * 4];
            *(float4*)&bf[0] = *(const float4*)&Bs[kk][tx * 4];
            *(float4*)&bf[4] = *(const float4*)&Bs[kk][64 + tx * 4];
#pragma unroll
            for (int i = 0; i < 8; i++)
#pragma unroll
                for (int j = 0; j < 8; j++)
                    acc[i][j] = fmaf(af[i], bf[j], acc[i][j]);
        }
        __syncthreads();
    }

    // Epilogue: rows {bm+ty*4+i, bm+64+ty*4+i}, cols {bn+tx*4+j, bn+64+tx*4+j}
#pragma unroll
    for (int ih = 0; ih < 2; ih++) {
#pragma unroll
        for (int i = 0; i < 4; i++) {
            int row = bm + ih * 64 + ty * 4 + i;
#pragma unroll
            for (int jh = 0; jh < 2; jh++) {
                int col = bn + jh * 64 + tx * 4;
                float4 v;
                v.x = acc[ih * 4 + i][jh * 4 + 0];
                v.y = acc[ih * 4 + i][jh * 4 + 1];
                v.z = acc[ih * 4 + i][jh * 4 + 2];
                v.w = acc[ih * 4 + i][jh * 4 + 3];
                if (HAS_SCALE) {
                    v.x *= alpha; v.y *= alpha; v.z *= alpha; v.w *= alpha;
                }
                if (HAS_BIAS) {
                    v.x += bias[col + 0];
                    v.y += bias[col + 1];
                    v.z += bias[col + 2];
                    v.w += bias[col + 3];
                }
                *(float4*)&C[(long long)row * ldc + col] = v;
            }
        }
    }
}

// ---------------------------------------------------------------------------
// Row softmax: one block per row of 2048, 256 threads x 8 elems (float4 pairs)
// ---------------------------------------------------------------------------
__global__ __launch_bounds__(256)
void softmax_rows(float* __restrict__ Sbuf)
{
    float* p = Sbuf + (size_t)blockIdx.x * SEQ;
    const int tid = threadIdx.x;

    float v[8];
    *(float4*)&v[0] = *(const float4*)&p[tid * 8 + 0];
    *(float4*)&v[4] = *(const float4*)&p[tid * 8 + 4];

    float mx = -1e30f;
#pragma unroll
    for (int i = 0; i < 8; i++) mx = fmaxf(mx, v[i]);

    __shared__ float red[8];
    __shared__ float bcast;
#pragma unroll
    for (int o = 16; o > 0; o >>= 1)
        mx = fmaxf(mx, __shfl_xor_sync(0xffffffffu, mx, o));
    if ((tid & 31) == 0) red[tid >> 5] = mx;
    __syncthreads();
    if (tid < 32) {
        float m = (tid < 8) ? red[tid] : -1e30f;
#pragma unroll
        for (int o = 4; o > 0; o >>= 1)
            m = fmaxf(m, __shfl_xor_sync(0xffffffffu, m, o));
        if (tid == 0) bcast = m;
    }
    __syncthreads();
    mx = bcast;
    __syncthreads();

    float sum = 0.f;
#pragma unroll
    for (int i = 0; i < 8; i++) { v[i] = expf(v[i] - mx); sum += v[i]; }

#pragma unroll
    for (int o = 16; o > 0; o >>= 1)
        sum += __shfl_xor_sync(0xffffffffu, sum, o);
    if ((tid & 31) == 0) red[tid >> 5] = sum;
    __syncthreads();
    if (tid < 32) {
        float s = (tid < 8) ? red[tid] : 0.f;
#pragma unroll
        for (int o = 4; o > 0; o >>= 1)
            s += __shfl_xor_sync(0xffffffffu, s, o);
        if (tid == 0) bcast = s;
    }
    __syncthreads();
    float inv = 1.0f / bcast;

#pragma unroll
    for (int i = 0; i < 8; i++) v[i] *= inv;
    *(float4*)&p[tid * 8 + 0] = *(const float4*)&v[0];
    *(float4*)&p[tid * 8 + 4] = *(const float4*)&v[4];
}

// ---------------------------------------------------------------------------
extern "C" void kernel_launch(void* const* d_in, const int* in_sizes, int n_in,
                              void* d_out, int out_size)
{
    const float* X  = (const float*)d_in[0];
    const float* Wq = (const float*)d_in[1];
    const float* bq = (const float*)d_in[2];
    const float* Wk = (const float*)d_in[3];
    const float* bk = (const float*)d_in[4];
    const float* Wv = (const float*)d_in[5];
    const float* bv = (const float*)d_in[6];
    float* out = (float*)d_out;

    float *Q, *K, *V, *Sc;
    cudaGetSymbolAddress((void**)&Q,  g_Q);
    cudaGetSymbolAddress((void**)&K,  g_K);
    cudaGetSymbolAddress((void**)&V,  g_V);
    cudaGetSymbolAddress((void**)&Sc, g_S);

    const float scale = 1.0f / sqrtf((float)DIM);

    // 1) QKV projections: [8192,512] @ [512,512] + bias  (NN)
    {
        dim3 grid(DIM / 128, (BATCH * SEQ) / 128, 1);
        sgemm128<false, true, false><<<grid, 256>>>(
            BATCH * SEQ, DIM, DIM, X, DIM, 0, Wq, DIM, 0, Q, DIM, 0, 1.0f, bq);
        sgemm128<false, true, false><<<grid, 256>>>(
            BATCH * SEQ, DIM, DIM, X, DIM, 0, Wk, DIM, 0, K, DIM, 0, 1.0f, bk);
        sgemm128<false, true, false><<<grid, 256>>>(
            BATCH * SEQ, DIM, DIM, X, DIM, 0, Wv, DIM, 0, V, DIM, 0, 1.0f, bv);
    }

    // 2) scores = Q @ K^T * 1/sqrt(d)   (NT), per batch via z
    {
        dim3 grid(SEQ / 128, SEQ / 128, BATCH);
        sgemm128<true, false, true><<<grid, 256>>>(
            SEQ, SEQ, DIM,
            Q, DIM, (long long)SEQ * DIM,
            K, DIM, (long long)SEQ * DIM,
            Sc, SEQ, (long long)SEQ * SEQ,
            scale, nullptr);
    }

    // 3) row softmax over 2048-wide rows (BATCH*SEQ rows)
    softmax_rows<<<BATCH * SEQ, 256>>>(Sc);

    // 4) out = P @ V   (NN), per batch via z
    {
        dim3 grid(DIM / 128, SEQ / 128, BATCH);
        sgemm128<false, false, false><<<grid, 256>>>(
            SEQ, DIM, SEQ,
            Sc, SEQ, (long long)SEQ * SEQ,
            V, DIM, (long long)SEQ * DIM,
            out, DIM, (long long)SEQ * DIM,
            1.0f, nullptr);
    }
}

// round 2
// speedup vs baseline: 2.8439x; 2.8439x over previous
#include <cuda_runtime.h>
#include <math.h>
#include <stdint.h>

#define BATCH 4
#define SEQ   2048
#define DIM   512

// Scratch (__device__ globals — allocation-free per harness rules)
__device__ float g_Q [BATCH * SEQ * DIM];           // 16 MB
__device__ float g_K [BATCH * SEQ * DIM];           // 16 MB
__device__ float g_V [BATCH * SEQ * DIM];           // 16 MB
__device__ float g_Vt[BATCH * SEQ * DIM];           // 16 MB (V transposed [b][d][t])
__device__ float g_Wt[DIM * DIM];                   // 1 MB (transposed weight, reused)
__device__ float g_S [(size_t)BATCH * SEQ * SEQ];   // 64 MB (scores / probs)

// ---------------------------------------------------------------------------
__device__ __forceinline__ float to_tf32(float x) {
    float y;
    asm("cvt.rna.tf32.f32 %0, %1;" : "=f"(y) : "f"(x));
    return y;
}

// ---------------------------------------------------------------------------
// Tiled transpose: out[c][r] = in[r][c], dims multiples of 32.
// blockIdx.z batches (stride rows*cols).
// ---------------------------------------------------------------------------
__global__ __launch_bounds__(256)
void transpose_k(const float* __restrict__ in, float* __restrict__ out,
                 int rows, int cols)
{
    __shared__ float tile[32][33];
    const long long zoff = (long long)blockIdx.z * rows * cols;
    int c = blockIdx.x * 32 + threadIdx.x;
    int r = blockIdx.y * 32 + threadIdx.y;
#pragma unroll
    for (int j = 0; j < 32; j += 8)
        tile[threadIdx.y + j][threadIdx.x] = in[zoff + (long long)(r + j) * cols + c];
    __syncthreads();
    int c2 = blockIdx.y * 32 + threadIdx.x;   // index into rows-dim
    int r2 = blockIdx.x * 32 + threadIdx.y;   // index into cols-dim
#pragma unroll
    for (int j = 0; j < 32; j += 8)
        out[zoff + (long long)(r2 + j) * rows + c2] = tile[threadIdx.x][threadIdx.y + j];
}

// ---------------------------------------------------------------------------
// TF32 tensor-core GEMM: C = alpha * A[MxK] @ B[NxK]^T (+bias)
// A row-major [M][K] (lda), B row-major [N][K] (ldb) -> mma .col B fragment.
// Block tile 128x128x32, 256 threads = 8 warps (2 x 4), warp tile 64x32.
// M,N multiples of 128; K multiple of 32. blockIdx.z batches via strides.
// ---------------------------------------------------------------------------
template <bool HAS_BIAS, bool HAS_SCALE>
__global__ __launch_bounds__(256, 2)
void tf32gemm(int M, int N, int K,
              const float* __restrict__ A, int lda, long long sA,
              const float* __restrict__ B, int ldb, long long sB,
              float* __restrict__ C, int ldc, long long sC,
              float alpha, const float* __restrict__ bias)
{
    A += (long long)blockIdx.z * sA;
    B += (long long)blockIdx.z * sB;
    C += (long long)blockIdx.z * sC;

    __shared__ float As[128][36];   // [m][k], ldk=36 -> conflict-free
    __shared__ float Bs[128][36];   // [n][k]

    const int tid   = threadIdx.x;
    const int wid   = tid >> 5;
    const int lane  = tid & 31;
    const int gID   = lane >> 2;    // 0..7
    const int tig   = lane & 3;     // 0..3
    const int warp_m = wid & 1;     // 2 warps along M
    const int warp_n = wid >> 1;    // 4 warps along N

    const int bm = blockIdx.y * 128;
    const int bn = blockIdx.x * 128;

    // Tile-load mapping: 1024 float4 per tile / 256 threads = 4 each.
    // lin = tid + i*256 ; row = lin>>3 (0..127) ; kq = lin&7 (float4 within 32 k)
    const int lrow = tid >> 3;
    const int lkq  = tid & 7;

    float acc[4][4][4];
#pragma unroll
    for (int mi = 0; mi < 4; mi++)
#pragma unroll
        for (int ni = 0; ni < 4; ni++)
#pragma unroll
            for (int t = 0; t < 4; t++) acc[mi][ni][t] = 0.f;

    for (int k0 = 0; k0 < K; k0 += 32) {
        // Load + convert A tile
#pragma unroll
        for (int i = 0; i < 4; i++) {
            int row = lrow + i * 32;
            float4 v = *(const float4*)&A[(long long)(bm + row) * lda + k0 + lkq * 4];
            float4 w;
            w.x = to_tf32(v.x); w.y = to_tf32(v.y);
            w.z = to_tf32(v.z); w.w = to_tf32(v.w);
            *(float4*)&As[row][lkq * 4] = w;
        }
        // Load + convert B tile
#pragma unroll
        for (int i = 0; i < 4; i++) {
            int row = lrow + i * 32;
            float4 v = *(const float4*)&B[(long long)(bn + row) * ldb + k0 + lkq * 4];
            float4 w;
            w.x = to_tf32(v.x); w.y = to_tf32(v.y);
            w.z = to_tf32(v.z); w.w = to_tf32(v.w);
            *(float4*)&Bs[row][lkq * 4] = w;
        }
        __syncthreads();

#pragma unroll
        for (int kk = 0; kk < 32; kk += 8) {
            uint32_t af[4][4], bf[4][2];
#pragma unroll
            for (int mi = 0; mi < 4; mi++) {
                int m = warp_m * 64 + mi * 16 + gID;
                af[mi][0] = __float_as_uint(As[m    ][kk + tig    ]);
                af[mi][1] = __float_as_uint(As[m + 8][kk + tig    ]);
                af[mi][2] = __float_as_uint(As[m    ][kk + tig + 4]);
                af[mi][3] = __float_as_uint(As[m + 8][kk + tig + 4]);
            }
#pragma unroll
            for (int ni = 0; ni < 4; ni++) {
                int n = warp_n * 32 + ni * 8 + gID;
                bf[ni][0] = __float_as_uint(Bs[n][kk + tig    ]);
                bf[ni][1] = __float_as_uint(Bs[n][kk + tig + 4]);
            }
#pragma unroll
            for (int mi = 0; mi < 4; mi++)
#pragma unroll
                for (int ni = 0; ni < 4; ni++) {
                    asm volatile(
                        "mma.sync.aligned.m16n8k8.row.col.f32.tf32.tf32.f32 "
                        "{%0,%1,%2,%3}, {%4,%5,%6,%7}, {%8,%9}, {%0,%1,%2,%3};\n"
                        : "+f"(acc[mi][ni][0]), "+f"(acc[mi][ni][1]),
                          "+f"(acc[mi][ni][2]), "+f"(acc[mi][ni][3])
                        : "r"(af[mi][0]), "r"(af[mi][1]),
                          "r"(af[mi][2]), "r"(af[mi][3]),
                          "r"(bf[ni][0]), "r"(bf[ni][1]));
                }
        }
        __syncthreads();
    }

    // Epilogue
#pragma unroll
    for (int mi = 0; mi < 4; mi++) {
#pragma unroll
        for (int ni = 0; ni < 4; ni++) {
            int r = bm + warp_m * 64 + mi * 16 + gID;
            int c = bn + warp_n * 32 + ni * 8 + tig * 2;
            float2 lo, hi;
            lo.x = acc[mi][ni][0]; lo.y = acc[mi][ni][1];
            hi.x = acc[mi][ni][2]; hi.y = acc[mi][ni][3];
            if (HAS_SCALE) {
                lo.x *= alpha; lo.y *= alpha; hi.x *= alpha; hi.y *= alpha;
            }
            if (HAS_BIAS) {
                float b0 = bias[c], b1 = bias[c + 1];
                lo.x += b0; lo.y += b1; hi.x += b0; hi.y += b1;
            }
            *(float2*)&C[(long long)r * ldc + c]       = lo;
            *(float2*)&C[(long long)(r + 8) * ldc + c] = hi;
        }
    }
}

// ---------------------------------------------------------------------------
// Row softmax: one block per row of 2048, 256 threads x 8 elems
// ---------------------------------------------------------------------------
__global__ __launch_bounds__(256)
void softmax_rows(float* __restrict__ Sbuf)
{
    float* p = Sbuf + (size_t)blockIdx.x * SEQ;
    const int tid = threadIdx.x;

    float v[8];
    *(float4*)&v[0] = *(const float4*)&p[tid * 8 + 0];
    *(float4*)&v[4] = *(const float4*)&p[tid * 8 + 4];

    float mx = -1e30f;
#pragma unroll
    for (int i = 0; i < 8; i++) mx = fmaxf(mx, v[i]);

    __shared__ float red[8];
    __shared__ float bcast;
#pragma unroll
    for (int o = 16; o > 0; o >>= 1)
        mx = fmaxf(mx, __shfl_xor_sync(0xffffffffu, mx, o));
    if ((tid & 31) == 0) red[tid >> 5] = mx;
    __syncthreads();
    if (tid < 32) {
        float m = (tid < 8) ? red[tid] : -1e30f;
#pragma unroll
        for (int o = 4; o > 0; o >>= 1)
            m = fmaxf(m, __shfl_xor_sync(0xffffffffu, m, o));
        if (tid == 0) bcast = m;
    }
    __syncthreads();
    mx = bcast;
    __syncthreads();

    float sum = 0.f;
#pragma unroll
    for (int i = 0; i < 8; i++) { v[i] = expf(v[i] - mx); sum += v[i]; }

#pragma unroll
    for (int o = 16; o > 0; o >>= 1)
        sum += __shfl_xor_sync(0xffffffffu, sum, o);
    if ((tid & 31) == 0) red[tid >> 5] = sum;
    __syncthreads();
    if (tid < 32) {
        float s = (tid < 8) ? red[tid] : 0.f;
#pragma unroll
        for (int o = 4; o > 0; o >>= 1)
            s += __shfl_xor_sync(0xffffffffu, s, o);
        if (tid == 0) bcast = s;
    }
    __syncthreads();
    float inv = 1.0f / bcast;

#pragma unroll
    for (int i = 0; i < 8; i++) v[i] *= inv;
    *(float4*)&p[tid * 8 + 0] = *(const float4*)&v[0];
    *(float4*)&p[tid * 8 + 4] = *(const float4*)&v[4];
}

// ---------------------------------------------------------------------------
extern "C" void kernel_launch(void* const* d_in, const int* in_sizes, int n_in,
                              void* d_out, int out_size)
{
    const float* X  = (const float*)d_in[0];
    const float* Wq = (const float*)d_in[1];
    const float* bq = (const float*)d_in[2];
    const float* Wk = (const float*)d_in[3];
    const float* bk = (const float*)d_in[4];
    const float* Wv = (const float*)d_in[5];
    const float* bv = (const float*)d_in[6];
    float* out = (float*)d_out;

    float *Q, *K, *V, *Vt, *Wt, *Sc;
    cudaGetSymbolAddress((void**)&Q,  g_Q);
    cudaGetSymbolAddress((void**)&K,  g_K);
    cudaGetSymbolAddress((void**)&V,  g_V);
    cudaGetSymbolAddress((void**)&Vt, g_Vt);
    cudaGetSymbolAddress((void**)&Wt, g_Wt);
    cudaGetSymbolAddress((void**)&Sc, g_S);

    const float scale = 1.0f / sqrtf((float)DIM);

    // 1) QKV projections. Transpose W (in[i][o] -> Wt[o][i]) then
    //    C[m][o] = X[m][:] . Wt[o][:]  (B-as-[N][K] form)
    {
        dim3 tgrid(DIM / 32, DIM / 32, 1);
        dim3 tblk(32, 8, 1);
        dim3 ggrid(DIM / 128, (BATCH * SEQ) / 128, 1);

        transpose_k<<<tgrid, tblk>>>(Wq, Wt, DIM, DIM);
        tf32gemm<true, false><<<ggrid, 256>>>(
            BATCH * SEQ, DIM, DIM, X, DIM, 0, Wt, DIM, 0, Q, DIM, 0, 1.0f, bq);

        transpose_k<<<tgrid, tblk>>>(Wk, Wt, DIM, DIM);
        tf32gemm<true, false><<<ggrid, 256>>>(
            BATCH * SEQ, DIM, DIM, X, DIM, 0, Wt, DIM, 0, K, DIM, 0, 1.0f, bk);

        transpose_k<<<tgrid, tblk>>>(Wv, Wt, DIM, DIM);
        tf32gemm<true, false><<<ggrid, 256>>>(
            BATCH * SEQ, DIM, DIM, X, DIM, 0, Wt, DIM, 0, V, DIM, 0, 1.0f, bv);
    }

    // 2) V transpose per batch: V[b][t][d] -> Vt[b][d][t]
    {
        dim3 tgrid(DIM / 32, SEQ / 32, BATCH);
        dim3 tblk(32, 8, 1);
        transpose_k<<<tgrid, tblk>>>(V, Vt, SEQ, DIM);
    }

    // 3) scores = Q @ K^T * 1/sqrt(d)  — K already [t][d] = [N][K]
    {
        dim3 grid(SEQ / 128, SEQ / 128, BATCH);
        tf32gemm<false, true><<<grid, 256>>>(
            SEQ, SEQ, DIM,
            Q, DIM, (long long)SEQ * DIM,
            K, DIM, (long long)SEQ * DIM,
            Sc, SEQ, (long long)SEQ * SEQ,
            scale, nullptr);
    }

    // 4) row softmax
    softmax_rows<<<BATCH * SEQ, 256>>>(Sc);

    // 5) out = P @ V  — uses Vt[b][d][t] = [N][K]
    {
        dim3 grid(DIM / 128, SEQ / 128, BATCH);
        tf32gemm<false, false><<<grid, 256>>>(
            SEQ, DIM, SEQ,
            Sc, SEQ, (long long)SEQ * SEQ,
            Vt, SEQ, (long long)SEQ * DIM,
            out, DIM, (long long)SEQ * DIM,
            1.0f, nullptr);
    }
}

// round 3
// speedup vs baseline: 3.2524x; 1.1437x over previous
#include <cuda_runtime.h>
#include <math.h>
#include <stdint.h>

#define BATCH 4
#define SEQ   2048
#define DIM   512

// Scratch (__device__ globals — allocation-free per harness rules)
__device__ float g_Xc [BATCH * SEQ * DIM];            // 16 MB  X, tf32-rounded
__device__ float g_QKV[3 * BATCH * SEQ * DIM];        // 48 MB  Q,K,V packed
__device__ float g_Vt [BATCH * SEQ * DIM];            // 16 MB  V^T [b][d][t]
__device__ float g_Wt [3 * DIM * DIM];                // 3 MB   W^T packed
__device__ float g_b3 [3 * DIM];                      // biases packed
__device__ float g_S  [(size_t)BATCH * SEQ * SEQ];    // 64 MB  scores/probs

// ---------------------------------------------------------------------------
__device__ __forceinline__ float to_tf32(float x) {
    float y;
    asm("cvt.rna.tf32.f32 %0, %1;" : "=f"(y) : "f"(x));
    return y;
}

// ---------------------------------------------------------------------------
// Convert-copy: out[i] = tf32(in[i]), n multiple of 1024
// ---------------------------------------------------------------------------
__global__ __launch_bounds__(256)
void cvt_copy(const float* __restrict__ in, float* __restrict__ out, int n4)
{
    int i = blockIdx.x * blockDim.x + threadIdx.x;
    if (i < n4) {
        float4 v = ((const float4*)in)[i];
        v.x = to_tf32(v.x); v.y = to_tf32(v.y);
        v.z = to_tf32(v.z); v.w = to_tf32(v.w);
        ((float4*)out)[i] = v;
    }
}

__global__ void pack_bias(const float* __restrict__ b0,
                          const float* __restrict__ b1,
                          const float* __restrict__ b2,
                          float* __restrict__ out)
{
    int i = threadIdx.x + blockIdx.x * blockDim.x;
    if (i < DIM) {
        out[i]           = b0[i];
        out[i + DIM]     = b1[i];
        out[i + 2 * DIM] = b2[i];
    }
}

// ---------------------------------------------------------------------------
// Tiled transpose with tf32 rounding: out[c][r] = tf32(in[r][c])
// ---------------------------------------------------------------------------
__global__ __launch_bounds__(256)
void transpose_cvt(const float* __restrict__ in, float* __restrict__ out,
                   int rows, int cols)
{
    __shared__ float tile[32][33];
    const long long zoff = (long long)blockIdx.z * rows * cols;
    int c = blockIdx.x * 32 + threadIdx.x;
    int r = blockIdx.y * 32 + threadIdx.y;
#pragma unroll
    for (int j = 0; j < 32; j += 8)
        tile[threadIdx.y + j][threadIdx.x] = in[zoff + (long long)(r + j) * cols + c];
    __syncthreads();
    int c2 = blockIdx.y * 32 + threadIdx.x;
    int r2 = blockIdx.x * 32 + threadIdx.y;
#pragma unroll
    for (int j = 0; j < 32; j += 8)
        out[zoff + (long long)(r2 + j) * rows + c2] =
            to_tf32(tile[threadIdx.x][threadIdx.y + j]);
}

// ---------------------------------------------------------------------------
// Pipelined TF32 tensor-core GEMM: C = alpha * A[MxK] @ B[NxK]^T (+bias)
// Inputs MUST already be tf32-rounded. cp.async double-buffered, tile
// 128x128x32, 256 threads (8 warps 2x4), warp tile 64x32.
// Dynamic smem: 2 stages * (A 128x36 + B 128x36) floats = 73728 B.
// ---------------------------------------------------------------------------
#define STAGE_F 9216   // floats per stage (4608 A + 4608 B)

__device__ __forceinline__ void cpa16(float* dst, const float* src)
{
    uint32_t d = (uint32_t)__cvta_generic_to_shared(dst);
    asm volatile("cp.async.cg.shared.global [%0], [%1], 16;" :: "r"(d), "l"(src));
}

template <bool HAS_BIAS, bool HAS_SCALE, bool CVT_OUT>
__global__ __launch_bounds__(256, 2)
void tf32gemm_pipe(int M, int N, int K,
                   const float* __restrict__ A, int lda, long long sA,
                   const float* __restrict__ B, int ldb, long long sB,
                   float* __restrict__ C, int ldc, long long sC,
                   float alpha, const float* __restrict__ bias, long long sBias)
{
    extern __shared__ float sm[];

    A += (long long)blockIdx.z * sA;
    B += (long long)blockIdx.z * sB;
    C += (long long)blockIdx.z * sC;
    if (HAS_BIAS) bias += (long long)blockIdx.z * sBias;

    const int tid    = threadIdx.x;
    const int wid    = tid >> 5;
    const int lane   = tid & 31;
    const int gID    = lane >> 2;
    const int tig    = lane & 3;
    const int warp_m = wid & 1;
    const int warp_n = wid >> 1;

    const int bm = blockIdx.y * 128;
    const int bn = blockIdx.x * 128;

    const int lrow = tid >> 3;       // 0..31
    const int lkq  = tid & 7;        // float4 index within 32-k

    const float* Ap = A + (long long)(bm + lrow) * lda + lkq * 4;
    const float* Bp = B + (long long)(bn + lrow) * ldb + lkq * 4;
    const int soff = lrow * 36 + lkq * 4;

    const int T = K >> 5;

    // Prologue: issue tile 0 into stage 0
    {
        float* sa = sm;
        float* sb = sm + 4608;
#pragma unroll
        for (int i = 0; i < 4; i++) {
            cpa16(sa + soff + i * 32 * 36, Ap + (long long)i * 32 * lda);
            cpa16(sb + soff + i * 32 * 36, Bp + (long long)i * 32 * ldb);
        }
        asm volatile("cp.async.commit_group;");
    }

    float acc[4][4][4];
#pragma unroll
    for (int mi = 0; mi < 4; mi++)
#pragma unroll
        for (int ni = 0; ni < 4; ni++)
#pragma unroll
            for (int t = 0; t < 4; t++) acc[mi][ni][t] = 0.f;

    for (int t = 0; t < T; t++) {
        if (t + 1 < T) {
            float* sa = sm + ((t + 1) & 1) * STAGE_F;
            float* sb = sa + 4608;
            const float* Apt = Ap + (t + 1) * 32;
            const float* Bpt = Bp + (t + 1) * 32;
#pragma unroll
            for (int i = 0; i < 4; i++) {
                cpa16(sa + soff + i * 32 * 36, Apt + (long long)i * 32 * lda);
                cpa16(sb + soff + i * 32 * 36, Bpt + (long long)i * 32 * ldb);
            }
            asm volatile("cp.async.commit_group;");
            asm volatile("cp.async.wait_group 1;");
        } else {
            asm volatile("cp.async.wait_group 0;");
        }
        __syncthreads();

        const float* As = sm + (t & 1) * STAGE_F;
        const float* Bs = As + 4608;

#pragma unroll
        for (int kk = 0; kk < 32; kk += 8) {
            uint32_t af[4][4], bf[4][2];
#pragma unroll
            for (int mi = 0; mi < 4; mi++) {
                int m = warp_m * 64 + mi * 16 + gID;
                af[mi][0] = __float_as_uint(As[m * 36 + kk + tig]);
                af[mi][1] = __float_as_uint(As[(m + 8) * 36 + kk + tig]);
                af[mi][2] = __float_as_uint(As[m * 36 + kk + tig + 4]);
                af[mi][3] = __float_as_uint(As[(m + 8) * 36 + kk + tig + 4]);
            }
#pragma unroll
            for (int ni = 0; ni < 4; ni++) {
                int n = warp_n * 32 + ni * 8 + gID;
                bf[ni][0] = __float_as_uint(Bs[n * 36 + kk + tig]);
                bf[ni][1] = __float_as_uint(Bs[n * 36 + kk + tig + 4]);
            }
#pragma unroll
            for (int mi = 0; mi < 4; mi++)
#pragma unroll
                for (int ni = 0; ni < 4; ni++) {
                    asm volatile(
                        "mma.sync.aligned.m16n8k8.row.col.f32.tf32.tf32.f32 "
                        "{%0,%1,%2,%3}, {%4,%5,%6,%7}, {%8,%9}, {%0,%1,%2,%3};\n"
                        : "+f"(acc[mi][ni][0]), "+f"(acc[mi][ni][1]),
                          "+f"(acc[mi][ni][2]), "+f"(acc[mi][ni][3])
                        : "r"(af[mi][0]), "r"(af[mi][1]),
                          "r"(af[mi][2]), "r"(af[mi][3]),
                          "r"(bf[ni][0]), "r"(bf[ni][1]));
                }
        }
        __syncthreads();
    }

    // Epilogue
#pragma unroll
    for (int mi = 0; mi < 4; mi++) {
#pragma unroll
        for (int ni = 0; ni < 4; ni++) {
            int r = bm + warp_m * 64 + mi * 16 + gID;
            int c = bn + warp_n * 32 + ni * 8 + tig * 2;
            float2 lo, hi;
            lo.x = acc[mi][ni][0]; lo.y = acc[mi][ni][1];
            hi.x = acc[mi][ni][2]; hi.y = acc[mi][ni][3];
            if (HAS_SCALE) {
                lo.x *= alpha; lo.y *= alpha; hi.x *= alpha; hi.y *= alpha;
            }
            if (HAS_BIAS) {
                float b0 = bias[c], b1 = bias[c + 1];
                lo.x += b0; lo.y += b1; hi.x += b0; hi.y += b1;
            }
            if (CVT_OUT) {
                lo.x = to_tf32(lo.x); lo.y = to_tf32(lo.y);
                hi.x = to_tf32(hi.x); hi.y = to_tf32(hi.y);
            }
            *(float2*)&C[(long long)r * ldc + c]       = lo;
            *(float2*)&C[(long long)(r + 8) * ldc + c] = hi;
        }
    }
}

// ---------------------------------------------------------------------------
// Row softmax; output rounded to tf32 (feeds PV GEMM as A operand)
// ---------------------------------------------------------------------------
__global__ __launch_bounds__(256)
void softmax_rows(float* __restrict__ Sbuf)
{
    float* p = Sbuf + (size_t)blockIdx.x * SEQ;
    const int tid = threadIdx.x;

    float v[8];
    *(float4*)&v[0] = *(const float4*)&p[tid * 8 + 0];
    *(float4*)&v[4] = *(const float4*)&p[tid * 8 + 4];

    float mx = -1e30f;
#pragma unroll
    for (int i = 0; i < 8; i++) mx = fmaxf(mx, v[i]);

    __shared__ float red[8];
    __shared__ float bcast;
#pragma unroll
    for (int o = 16; o > 0; o >>= 1)
        mx = fmaxf(mx, __shfl_xor_sync(0xffffffffu, mx, o));
    if ((tid & 31) == 0) red[tid >> 5] = mx;
    __syncthreads();
    if (tid < 32) {
        float m = (tid < 8) ? red[tid] : -1e30f;
#pragma unroll
        for (int o = 4; o > 0; o >>= 1)
            m = fmaxf(m, __shfl_xor_sync(0xffffffffu, m, o));
        if (tid == 0) bcast = m;
    }
    __syncthreads();
    mx = bcast;
    __syncthreads();

    float sum = 0.f;
#pragma unroll
    for (int i = 0; i < 8; i++) { v[i] = expf(v[i] - mx); sum += v[i]; }

#pragma unroll
    for (int o = 16; o > 0; o >>= 1)
        sum += __shfl_xor_sync(0xffffffffu, sum, o);
    if ((tid & 31) == 0) red[tid >> 5] = sum;
    __syncthreads();
    if (tid < 32) {
        float s = (tid < 8) ? red[tid] : 0.f;
#pragma unroll
        for (int o = 4; o > 0; o >>= 1)
            s += __shfl_xor_sync(0xffffffffu, s, o);
        if (tid == 0) bcast = s;
    }
    __syncthreads();
    float inv = 1.0f / bcast;

#pragma unroll
    for (int i = 0; i < 8; i++) v[i] = to_tf32(v[i] * inv);
    *(float4*)&p[tid * 8 + 0] = *(const float4*)&v[0];
    *(float4*)&p[tid * 8 + 4] = *(const float4*)&v[4];
}

// ---------------------------------------------------------------------------
extern "C" void kernel_launch(void* const* d_in, const int* in_sizes, int n_in,
                              void* d_out, int out_size)
{
    const float* X  = (const float*)d_in[0];
    const float* Wq = (const float*)d_in[1];
    const float* bq = (const float*)d_in[2];
    const float* Wk = (const float*)d_in[3];
    const float* bk = (const float*)d_in[4];
    const float* Wv = (const float*)d_in[5];
    const float* bv = (const float*)d_in[6];
    float* out = (float*)d_out;

    float *Xc, *QKV, *Vt, *Wt, *b3, *Sc;
    cudaGetSymbolAddress((void**)&Xc,  g_Xc);
    cudaGetSymbolAddress((void**)&QKV, g_QKV);
    cudaGetSymbolAddress((void**)&Vt,  g_Vt);
    cudaGetSymbolAddress((void**)&Wt,  g_Wt);
    cudaGetSymbolAddress((void**)&b3,  g_b3);
    cudaGetSymbolAddress((void**)&Sc,  g_S);

    const float scale = 1.0f / sqrtf((float)DIM);
    const long long QKVs = (long long)BATCH * SEQ * DIM;
    const int SMEM = 2 * STAGE_F * 4;   // 73728 B

    static bool attr_set = false;
    if (!attr_set) {
        cudaFuncSetAttribute(tf32gemm_pipe<true, false, true>,
                             cudaFuncAttributeMaxDynamicSharedMemorySize, SMEM);
        cudaFuncSetAttribute(tf32gemm_pipe<false, true, false>,
                             cudaFuncAttributeMaxDynamicSharedMemorySize, SMEM);
        cudaFuncSetAttribute(tf32gemm_pipe<false, false, false>,
                             cudaFuncAttributeMaxDynamicSharedMemorySize, SMEM);
        attr_set = true;
    }

    // 0) Pre-round X; pack + transpose weights; pack biases
    {
        int n4 = BATCH * SEQ * DIM / 4;
        cvt_copy<<<(n4 + 255) / 256, 256>>>(X, Xc, n4);

        dim3 tgrid(DIM / 32, DIM / 32, 1);
        dim3 tblk(32, 8, 1);
        transpose_cvt<<<tgrid, tblk>>>(Wq, Wt,               DIM, DIM);
        transpose_cvt<<<tgrid, tblk>>>(Wk, Wt + DIM * DIM,   DIM, DIM);
        transpose_cvt<<<tgrid, tblk>>>(Wv, Wt + 2 * DIM * DIM, DIM, DIM);
        pack_bias<<<2, 256>>>(bq, bk, bv, b3);
    }

    // 1) Fused QKV projections: z in {0,1,2}
    {
        dim3 grid(DIM / 128, (BATCH * SEQ) / 128, 3);
        tf32gemm_pipe<true, false, true><<<grid, 256, SMEM>>>(
            BATCH * SEQ, DIM, DIM,
            Xc, DIM, 0,
            Wt, DIM, (long long)DIM * DIM,
            QKV, DIM, QKVs,
            1.0f, b3, DIM);
    }

    // 2) V transpose per batch: V[b][t][d] -> Vt[b][d][t] (with re-round)
    {
        dim3 tgrid(DIM / 32, SEQ / 32, BATCH);
        dim3 tblk(32, 8, 1);
        transpose_cvt<<<tgrid, tblk>>>(QKV + 2 * QKVs, Vt, SEQ, DIM);
    }

    // 3) scores = Q @ K^T * 1/sqrt(d)
    {
        dim3 grid(SEQ / 128, SEQ / 128, BATCH);
        tf32gemm_pipe<false, true, false><<<grid, 256, SMEM>>>(
            SEQ, SEQ, DIM,
            QKV, DIM, (long long)SEQ * DIM,
            QKV + QKVs, DIM, (long long)SEQ * DIM,
            Sc, SEQ, (long long)SEQ * SEQ,
            scale, nullptr, 0);
    }

    // 4) row softmax (writes tf32-rounded P)
    softmax_rows<<<BATCH * SEQ, 256>>>(Sc);

    // 5) out = P @ V  (B = Vt[b][d][t] = [N][K])
    {
        dim3 grid(DIM / 128, SEQ / 128, BATCH);
        tf32gemm_pipe<false, false, false><<<grid, 256, SMEM>>>(
            SEQ, DIM, SEQ,
            Sc, SEQ, (long long)SEQ * SEQ,
            Vt, SEQ, (long long)SEQ * DIM,
            out, DIM, (long long)SEQ * DIM,
            1.0f, nullptr, 0);
    }
}